// round 12
// baseline (speedup 1.0000x reference)
#include <cuda_runtime.h>
#include <cuda_bf16.h>
#include <cstdint>

// ---------------------------------------------------------------------------
// RelNet forward, GB300 (sm_103a; harness lowers to sm_103 -> mma.sync only).
// h1(n,i,j) = relu(rowA[n,i] + rowB[n,j] + qc[n])  (layer-1 factorization)
// Layers 2-4: fused bf16 m16n8k16 MMA per 128-pair tile; weights streamed
// through a 4-deep KC=64 cp.async ring (1 barrier/chunk, depth-3 prefetch).
// fp32 column sums -> mean -> parallel f-MLP -> log_softmax.
// ---------------------------------------------------------------------------

#define NB   64
#define OO   64
#define GD   256
#define DD   66
#define NCTA 2048                    // 64 batches * 32 row tiles (2 i x 64 j)
#define AS   264                     // bf16 elems per smem row (256 + 8 pad)
#define KC   64                      // weight rows per ring chunk
#define SM_MAIN ((128*AS + 4*KC*AS)*2)         // 202752 B, occ 1
#define SM_PRE  ((DD*256 + DD*64)*4)           // 84480 B,  occ 2

// --------------------------- device scratch --------------------------------
__device__ float d_rowA[NB*OO*GD];
__device__ float d_rowB[NB*OO*GD];
__device__ float d_qc  [NB*GD];
__device__ __nv_bfloat16 d_w2b[GD*GD];
__device__ __nv_bfloat16 d_w3b[GD*GD];
__device__ __nv_bfloat16 d_w4b[GD*GD];
__device__ float d_partial[NCTA*GD];

__device__ __forceinline__ void ldsm_x4(unsigned* r, unsigned addr) {
    asm volatile("ldmatrix.sync.aligned.m8n8.x4.shared.b16 {%0,%1,%2,%3}, [%4];"
                 : "=r"(r[0]), "=r"(r[1]), "=r"(r[2]), "=r"(r[3]) : "r"(addr));
}
__device__ __forceinline__ void ldsm_x4_t(unsigned* r, unsigned addr) {
    asm volatile("ldmatrix.sync.aligned.m8n8.x4.trans.shared.b16 {%0,%1,%2,%3}, [%4];"
                 : "=r"(r[0]), "=r"(r[1]), "=r"(r[2]), "=r"(r[3]) : "r"(addr));
}
__device__ __forceinline__ void mma_bf16(float* c, const unsigned* a,
                                         unsigned b0, unsigned b1) {
    asm volatile(
        "mma.sync.aligned.m16n8k16.row.col.f32.bf16.bf16.f32 "
        "{%0,%1,%2,%3}, {%4,%5,%6,%7}, {%8,%9}, {%0,%1,%2,%3};"
        : "+f"(c[0]), "+f"(c[1]), "+f"(c[2]), "+f"(c[3])
        : "r"(a[0]), "r"(a[1]), "r"(a[2]), "r"(a[3]), "r"(b0), "r"(b1));
}

// ---------------------------------------------------------------------------
// rn_pre: grid 320 x 512 (proven 22us config).
//   bx < 256 : rowA/rowB CTA (n=bx>>2, half, ihalf), weight slab in smem.
//   bx >= 256: qc CTA per batch, k-split x2, ILP x4.
//   First 192 CTAs convert one float2 of g-weights to bf16 each.
// ---------------------------------------------------------------------------
__global__ void __launch_bounds__(512)
rn_pre(const float* __restrict__ img, const float* __restrict__ ques,
       const float* __restrict__ gw1, const float* __restrict__ gb1,
       const float* __restrict__ w2, const float* __restrict__ w3,
       const float* __restrict__ w4) {
    extern __shared__ float fsm[];
    const int bx = blockIdx.x;
    const int t  = threadIdx.x;

    {
        const int gt = bx*512 + t;
        if (gt < 3*32768) {
            int m   = gt >> 15;
            int off = (gt & 32767) * 2;
            const float* src = (m == 0) ? w2 : (m == 1) ? w3 : w4;
            __nv_bfloat16* dst = (m == 0) ? d_w2b : (m == 1) ? d_w3b : d_w4b;
            float2 v = *(const float2*)(src + off);
            *(__nv_bfloat162*)(dst + off) = __floats2bfloat162_rn(v.x, v.y);
        }
    }

    if (bx < 256) {
        float* wsm = fsm;                 // [66][256]
        float* csm = fsm + DD*256;        // [66][64]
        const int n     = bx >> 2;
        const int half  = (bx >> 1) & 1;
        const int ihalf = bx & 1;

        const float4* wsrc = (const float4*)(gw1 + half*DD*256);
        for (int i = t; i < DD*256/4; i += 512)
            ((float4*)wsm)[i] = wsrc[i];
        for (int idx = t; idx < DD*OO; idx += 512) {
            int d = idx >> 6, i = idx & 63;
            float v;
            if (d < 64)       v = img[(n*64 + d)*64 + i];
            else if (d == 64) v = (float)(i >> 3);
            else              v = (float)(i & 7);
            csm[d*64 + i] = v;
        }
        __syncthreads();

        const int g   = t & 255;
        const int ith = t >> 8;                   // 0..1
        float* out = half ? d_rowB : d_rowA;

        #pragma unroll
        for (int it2 = 0; it2 < 2; ++it2) {
            const int it = ihalf*4 + ith*2 + it2; // 0..7
            float acc[8];
            #pragma unroll
            for (int ii = 0; ii < 8; ++ii) acc[ii] = 0.f;
            #pragma unroll 2
            for (int d = 0; d < DD; ++d) {
                float w = wsm[d*256 + g];
                float4 c0 = *(const float4*)(csm + d*64 + it*8);
                float4 c1 = *(const float4*)(csm + d*64 + it*8 + 4);
                acc[0] += c0.x * w; acc[1] += c0.y * w;
                acc[2] += c0.z * w; acc[3] += c0.w * w;
                acc[4] += c1.x * w; acc[5] += c1.y * w;
                acc[6] += c1.z * w; acc[7] += c1.w * w;
            }
            #pragma unroll
            for (int ii = 0; ii < 8; ++ii)
                out[(n*OO + it*8 + ii)*GD + g] = acc[ii];
        }
    } else {
        float* qsm = fsm;                 // [256]
        float* red = fsm + 256;           // [2][256]
        const int n  = bx - 256;
        const int ks = t >> 8;
        const int g  = t & 255;

        if (t < 256) qsm[t] = ques[n*GD + t];
        __syncthreads();

        const float* base = gw1 + (2*DD + ks*128)*GD + g;
        const float* qb   = qsm + ks*128;
        float a0 = 0.f, a1 = 0.f, a2 = 0.f, a3 = 0.f;
        #pragma unroll 8
        for (int e = 0; e < 128; e += 4) {
            a0 += qb[e]     * base[(e)    *GD];
            a1 += qb[e + 1] * base[(e + 1)*GD];
            a2 += qb[e + 2] * base[(e + 2)*GD];
            a3 += qb[e + 3] * base[(e + 3)*GD];
        }
        red[ks*256 + g] = (a0 + a1) + (a2 + a3);
        __syncthreads();
        if (t < 256)
            d_qc[n*GD + t] = red[t] + red[256 + t] + gb1[t];
    }
}

// ---------------------------------------------------------------------------
// rn_main: fused layers 2-4 per 128-pair tile. grid 2048, 512 threads.
// A tile 128x256 bf16; weights in a 4-deep KC=64 cp.async ring.
// Warp grid 2x8, warp tile 64x32, mma m16n8k16 bf16 via ldmatrix.
// One barrier per chunk (issue AFTER the barrier; slot (c+3)%4's last
// readers ran in chunk c-1, ordered by chunk c's barrier).
// ---------------------------------------------------------------------------
__global__ void __launch_bounds__(512, 1)
rn_main(const float* __restrict__ b2, const float* __restrict__ b3,
        const float* __restrict__ b4) {
    extern __shared__ __nv_bfloat16 sm[];
    __nv_bfloat16* Asm = sm;                      // [128][AS]
    const unsigned AsmS = (unsigned)__cvta_generic_to_shared(sm);
    const unsigned BsmS = AsmS + (unsigned)(128*AS*2);

    const int n    = blockIdx.x >> 5;
    const int i0   = (blockIdx.x & 31) << 1;
    const int tid  = threadIdx.x;
    const int lane = tid & 31;
    const int warp = tid >> 5;
    const int wm   = warp >> 3;                   // 0..1 -> 64-row block
    const int wn   = warp & 7;                    // 0..7 -> 32-col block

    // chunk c (0..11): layer c/4, k-quarter c&3. Ring slot = c&3 (4-deep).
    auto issue = [&](int c) {
        const __nv_bfloat16* W = (c < 4) ? d_w2b : (c < 8) ? d_w3b : d_w4b;
        const __nv_bfloat16* src = W + (c & 3) * KC * GD;
        unsigned dst = BsmS + (unsigned)((c & 3) * KC * AS * 2);
        #pragma unroll
        for (int q = 0; q < 4; ++q) {
            int idx = q * 512 + tid;              // 0..2047
            int r = idx >> 5, s = idx & 31;
            unsigned sa = dst + (unsigned)(r * AS + s * 8) * 2u;
            asm volatile("cp.async.cg.shared.global [%0], [%1], 16;"
                         :: "r"(sa), "l"(src + r * GD + s * 8));
        }
        asm volatile("cp.async.commit_group;");
    };

    issue(0);   // slot 0 in flight while we build h1

    // ---- stage 1: h1 = relu(rowA_i + rowB_j + qc) -> bf16 A tile ----
    {
        const int g  = (tid & 127) * 2;
        const int r0 = tid >> 7;                  // 0..3
        const float2 qv = *(const float2*)(d_qc + n*GD + g);
        float2 A0 = *(const float2*)(d_rowA + (n*OO + i0    )*GD + g);
        float2 A1 = *(const float2*)(d_rowA + (n*OO + i0 + 1)*GD + g);
        A0.x += qv.x; A0.y += qv.y; A1.x += qv.x; A1.y += qv.y;
        #pragma unroll 4
        for (int s = 0; s < 32; ++s) {
            int r = r0 + s*4;
            int j = r & 63;
            float2 B = *(const float2*)(d_rowB + (n*OO + j)*GD + g);
            float vx = ((r >> 6) ? A1.x : A0.x) + B.x;
            float vy = ((r >> 6) ? A1.y : A0.y) + B.y;
            *(__nv_bfloat162*)(Asm + r*AS + g) =
                __floats2bfloat162_rn(fmaxf(vx, 0.f), fmaxf(vy, 0.f));
        }
    }

    issue(1);   // slots 1,2 never previously read -> safe to issue now
    issue(2);

    #pragma unroll 1
    for (int layer = 0; layer < 3; ++layer) {
        float C[4][4][4];
        #pragma unroll
        for (int mt = 0; mt < 4; ++mt)
            #pragma unroll
            for (int nt = 0; nt < 4; ++nt) {
                C[mt][nt][0] = 0.f; C[mt][nt][1] = 0.f;
                C[mt][nt][2] = 0.f; C[mt][nt][3] = 0.f;
            }

        #pragma unroll 1
        for (int ch = 0; ch < 4; ++ch) {
            const int c = layer*4 + ch;
            // chunk c needs group c complete; allow 2 younger groups pending.
            if (c < 10)      asm volatile("cp.async.wait_group 2;");
            else if (c == 10) asm volatile("cp.async.wait_group 1;");
            else              asm volatile("cp.async.wait_group 0;");
            __syncthreads();          // buffer c ready; chunk c-1 reads done;
                                      // stage-1 / epilogue A writes visible
            if (c < 9) issue(c + 3);  // slot (c+3)&3 last read in chunk c-1

            const unsigned bufS = BsmS + (unsigned)((c & 3) * KC * AS * 2);
            #pragma unroll
            for (int ksl = 0; ksl < 4; ++ksl) {
                const int kb = (c & 3)*KC + ksl*16;
                unsigned a[4][4];
                #pragma unroll
                for (int mt = 0; mt < 4; ++mt) {
                    unsigned ad = AsmS +
                        (unsigned)((wm*64 + mt*16 + (lane & 15))*AS
                                   + kb + ((lane >> 4) * 8)) * 2u;
                    ldsm_x4(a[mt], ad);
                }
                unsigned bfr[2][4];
                #pragma unroll
                for (int pr = 0; pr < 2; ++pr) {
                    unsigned bd = bufS +
                        (unsigned)((ksl*16 + (lane & 15))*AS
                                   + wn*32 + pr*16 + ((lane >> 4) * 8)) * 2u;
                    ldsm_x4_t(bfr[pr], bd);
                }
                #pragma unroll
                for (int mt = 0; mt < 4; ++mt) {
                    #pragma unroll
                    for (int pr = 0; pr < 2; ++pr) {
                        mma_bf16(C[mt][pr*2    ], a[mt], bfr[pr][0], bfr[pr][1]);
                        mma_bf16(C[mt][pr*2 + 1], a[mt], bfr[pr][2], bfr[pr][3]);
                    }
                }
            }
        }
        __syncthreads();              // all warps done reading A this layer

        if (layer < 2) {
            // epilogue: bias + relu -> bf16, in place into A tile.
            // Next chunk's top barrier publishes these writes to LDSM readers.
            const float* bias = (layer == 0) ? b2 : b3;
            #pragma unroll
            for (int mt = 0; mt < 4; ++mt) {
                #pragma unroll
                for (int nt = 0; nt < 4; ++nt) {
                    int row = wm*64 + mt*16 + (lane >> 2);
                    int col = wn*32 + nt*8 + (lane & 3)*2;
                    float2 bb = *(const float2*)(bias + col);
                    float v0 = fmaxf(C[mt][nt][0] + bb.x, 0.f);
                    float v1 = fmaxf(C[mt][nt][1] + bb.y, 0.f);
                    float v2 = fmaxf(C[mt][nt][2] + bb.x, 0.f);
                    float v3 = fmaxf(C[mt][nt][3] + bb.y, 0.f);
                    *(__nv_bfloat162*)(Asm + row*AS + col)     = __floats2bfloat162_rn(v0, v1);
                    *(__nv_bfloat162*)(Asm + (row+8)*AS + col) = __floats2bfloat162_rn(v2, v3);
                }
            }
        } else {
            // layer 4: bias + relu + column sum straight from fp32 registers
            float* stg = (float*)Asm;    // A tile dead; 2x256 fp32 staging
            #pragma unroll
            for (int nt = 0; nt < 4; ++nt) {
                int col = wn*32 + nt*8 + (lane & 3)*2;
                float2 bb = *(const float2*)(b4 + col);
                float s0 = 0.f, s1 = 0.f;
                #pragma unroll
                for (int mt = 0; mt < 4; ++mt) {
                    s0 += fmaxf(C[mt][nt][0] + bb.x, 0.f)
                        + fmaxf(C[mt][nt][2] + bb.x, 0.f);
                    s1 += fmaxf(C[mt][nt][1] + bb.y, 0.f)
                        + fmaxf(C[mt][nt][3] + bb.y, 0.f);
                }
                #pragma unroll
                for (int off = 16; off >= 4; off >>= 1) {
                    s0 += __shfl_down_sync(0xffffffffu, s0, off);
                    s1 += __shfl_down_sync(0xffffffffu, s1, off);
                }
                if (lane < 4) {
                    int cc = wn*32 + nt*8 + lane*2;
                    stg[wm*GD + cc]     = s0;
                    stg[wm*GD + cc + 1] = s1;
                }
            }
            __syncthreads();
            if (tid < GD)
                d_partial[blockIdx.x*GD + tid] = stg[tid] + stg[GD + tid];
        }
    }
}

// ---------------------------------------------------------------------------
// rn_post: mean -> f-MLP -> log_softmax. grid 64, 1024 threads, k-split x4.
// ---------------------------------------------------------------------------
__global__ void __launch_bounds__(1024, 1)
rn_post(const float* __restrict__ fw1, const float* __restrict__ fb1,
        const float* __restrict__ fw2, const float* __restrict__ fb2,
        const float* __restrict__ fw3, const float* __restrict__ fb3,
        float* __restrict__ out) {
    __shared__ float ctx[GD], acc[1024], y1s[GD], y2s[GD], red[16];
    const int n   = blockIdx.x;
    const int t   = threadIdx.x;
    const int col = t & 255;
    const int q   = t >> 8;                        // k-quarter 0..3

    {
        const float* base = d_partial + (n*32 + q*8)*GD + col;
        float s = 0.f;
        #pragma unroll
        for (int p = 0; p < 8; ++p) s += base[p*GD];
        acc[t] = s;
    }
    __syncthreads();
    if (t < GD)
        ctx[t] = (acc[t] + acc[t+256] + acc[t+512] + acc[t+768]) * (1.0f/4096.0f);
    __syncthreads();

    {
        float a0 = 0.f, a1 = 0.f;
        const float* w = fw1 + (q*64)*GD + col;
        #pragma unroll 8
        for (int k = 0; k < 64; k += 2) {
            a0 += ctx[q*64 + k]     * w[k*GD];
            a1 += ctx[q*64 + k + 1] * w[(k+1)*GD];
        }
        acc[t] = a0 + a1;
    }
    __syncthreads();
    if (t < GD)
        y1s[t] = fmaxf(acc[t] + acc[t+256] + acc[t+512] + acc[t+768] + fb1[t], 0.f);
    __syncthreads();

    {
        float a0 = 0.f, a1 = 0.f;
        const float* w = fw2 + (q*64)*GD + col;
        #pragma unroll 8
        for (int k = 0; k < 64; k += 2) {
            a0 += y1s[q*64 + k]     * w[k*GD];
            a1 += y1s[q*64 + k + 1] * w[(k+1)*GD];
        }
        acc[t] = a0 + a1;
    }
    __syncthreads();
    if (t < GD)
        y2s[t] = fmaxf(acc[t] + acc[t+256] + acc[t+512] + acc[t+768] + fb2[t], 0.f);
    __syncthreads();

    if (t < GD) {
        float p0 = y2s[t] * fw3[t*2 + 0];
        float p1 = y2s[t] * fw3[t*2 + 1];
        #pragma unroll
        for (int o = 16; o > 0; o >>= 1) {
            p0 += __shfl_down_sync(0xffffffffu, p0, o);
            p1 += __shfl_down_sync(0xffffffffu, p1, o);
        }
        if ((t & 31) == 0) { red[t >> 5] = p0; red[8 + (t >> 5)] = p1; }
    }
    __syncthreads();
    if (t == 0) {
        float s0 = fb3[0], s1 = fb3[1];
        #pragma unroll
        for (int w = 0; w < 8; ++w) { s0 += red[w]; s1 += red[8 + w]; }
        float m   = fmaxf(s0, s1);
        float lse = m + logf(expf(s0 - m) + expf(s1 - m));
        out[n*2 + 0] = s0 - lse;
        out[n*2 + 1] = s1 - lse;
    }
}

// ---------------------------------------------------------------------------
extern "C" void kernel_launch(void* const* d_in, const int* in_sizes, int n_in,
                              void* d_out, int out_size) {
    (void)in_sizes; (void)n_in; (void)out_size;
    const float* img  = (const float*)d_in[0];
    const float* ques = (const float*)d_in[1];
    const float* gw1  = (const float*)d_in[2];
    const float* gb1  = (const float*)d_in[3];
    const float* gw2  = (const float*)d_in[4];
    const float* gb2  = (const float*)d_in[5];
    const float* gw3  = (const float*)d_in[6];
    const float* gb3  = (const float*)d_in[7];
    const float* gw4  = (const float*)d_in[8];
    const float* gb4  = (const float*)d_in[9];
    const float* fw1  = (const float*)d_in[10];
    const float* fb1  = (const float*)d_in[11];
    const float* fw2  = (const float*)d_in[12];
    const float* fb2  = (const float*)d_in[13];
    const float* fw3  = (const float*)d_in[14];
    const float* fb3  = (const float*)d_in[15];
    float* out = (float*)d_out;

    cudaFuncSetAttribute(rn_pre,  cudaFuncAttributeMaxDynamicSharedMemorySize, SM_PRE);
    cudaFuncSetAttribute(rn_main, cudaFuncAttributeMaxDynamicSharedMemorySize, SM_MAIN);

    rn_pre  <<<320, 512, SM_PRE>>>(img, ques, gw1, gb1, gw2, gw3, gw4);
    rn_main <<<NCTA, 512, SM_MAIN>>>(gb2, gb3, gb4);
    rn_post <<<NB, 1024>>>(fw1, fb1, fw2, fb2, fw3, fb3, out);
}

// round 13
// speedup vs baseline: 1.0712x; 1.0712x over previous
#include <cuda_runtime.h>
#include <cuda_bf16.h>
#include <cstdint>

// ---------------------------------------------------------------------------
// RelNet forward, GB300 (sm_103a; harness lowers to sm_103 -> mma.sync only).
// h1(n,i,j) = relu(rowA[n,i] + rowB[n,j] + qc[n])  (layer-1 factorization)
// Layers 2-4: fused bf16 m16n8k16 MMA per 128-pair tile. Weights staged
// PER WARP-PAIR (warp (0,wn) loads the 32-column slice both (0,wn) and
// (1,wn) consume) with 2-warp named barriers -> no full-CTA coupling on
// the weight stream. fp32 column sums -> mean -> f-MLP -> log_softmax.
// ---------------------------------------------------------------------------

#define NB   64
#define OO   64
#define GD   256
#define DD   66
#define NCTA 2048                    // 64 batches * 32 row tiles (2 i x 64 j)
#define AS   264                     // bf16 elems per smem A row (256 + 8 pad)
#define KC   64                      // weight rows per chunk
#define BSTR 40                      // bf16 elems per slice row (32 + 8 pad)
#define SLICE_B (KC*BSTR*2)          // 5120 B per slice buffer
#define BO   (128*AS*2)              // slice region base (after A tile)
#define SM_MAIN (BO + 16*SLICE_B)    // 67584 + 81920 = 149504 B, occ 1
#define SM_PRE  ((DD*256 + DD*64)*4) // 84480 B, occ 2

// --------------------------- device scratch --------------------------------
__device__ float d_rowA[NB*OO*GD];
__device__ float d_rowB[NB*OO*GD];
__device__ float d_qc  [NB*GD];
__device__ __nv_bfloat16 d_w2b[GD*GD];   // [k][n] row-major
__device__ __nv_bfloat16 d_w3b[GD*GD];
__device__ __nv_bfloat16 d_w4b[GD*GD];
__device__ float d_partial[NCTA*GD];

__device__ __forceinline__ void ldsm_x4(unsigned* r, unsigned addr) {
    asm volatile("ldmatrix.sync.aligned.m8n8.x4.shared.b16 {%0,%1,%2,%3}, [%4];"
                 : "=r"(r[0]), "=r"(r[1]), "=r"(r[2]), "=r"(r[3]) : "r"(addr));
}
__device__ __forceinline__ void ldsm_x4_t(unsigned* r, unsigned addr) {
    asm volatile("ldmatrix.sync.aligned.m8n8.x4.trans.shared.b16 {%0,%1,%2,%3}, [%4];"
                 : "=r"(r[0]), "=r"(r[1]), "=r"(r[2]), "=r"(r[3]) : "r"(addr));
}
__device__ __forceinline__ void mma_bf16(float* c, const unsigned* a,
                                         unsigned b0, unsigned b1) {
    asm volatile(
        "mma.sync.aligned.m16n8k16.row.col.f32.bf16.bf16.f32 "
        "{%0,%1,%2,%3}, {%4,%5,%6,%7}, {%8,%9}, {%0,%1,%2,%3};"
        : "+f"(c[0]), "+f"(c[1]), "+f"(c[2]), "+f"(c[3])
        : "r"(a[0]), "r"(a[1]), "r"(a[2]), "r"(a[3]), "r"(b0), "r"(b1));
}
__device__ __forceinline__ void bar_pair(int id) {
    asm volatile("bar.sync %0, 64;" :: "r"(id) : "memory");
}

// ---------------------------------------------------------------------------
// rn_pre: grid 320 x 512 (proven 22us config).
// ---------------------------------------------------------------------------
__global__ void __launch_bounds__(512)
rn_pre(const float* __restrict__ img, const float* __restrict__ ques,
       const float* __restrict__ gw1, const float* __restrict__ gb1,
       const float* __restrict__ w2, const float* __restrict__ w3,
       const float* __restrict__ w4) {
    extern __shared__ float fsm[];
    const int bx = blockIdx.x;
    const int t  = threadIdx.x;

    {
        const int gt = bx*512 + t;
        if (gt < 3*32768) {
            int m   = gt >> 15;
            int off = (gt & 32767) * 2;
            const float* src = (m == 0) ? w2 : (m == 1) ? w3 : w4;
            __nv_bfloat16* dst = (m == 0) ? d_w2b : (m == 1) ? d_w3b : d_w4b;
            float2 v = *(const float2*)(src + off);
            *(__nv_bfloat162*)(dst + off) = __floats2bfloat162_rn(v.x, v.y);
        }
    }

    if (bx < 256) {
        float* wsm = fsm;                 // [66][256]
        float* csm = fsm + DD*256;        // [66][64]
        const int n     = bx >> 2;
        const int half  = (bx >> 1) & 1;
        const int ihalf = bx & 1;

        const float4* wsrc = (const float4*)(gw1 + half*DD*256);
        for (int i = t; i < DD*256/4; i += 512)
            ((float4*)wsm)[i] = wsrc[i];
        for (int idx = t; idx < DD*OO; idx += 512) {
            int d = idx >> 6, i = idx & 63;
            float v;
            if (d < 64)       v = img[(n*64 + d)*64 + i];
            else if (d == 64) v = (float)(i >> 3);
            else              v = (float)(i & 7);
            csm[d*64 + i] = v;
        }
        __syncthreads();

        const int g   = t & 255;
        const int ith = t >> 8;                   // 0..1
        float* out = half ? d_rowB : d_rowA;

        #pragma unroll
        for (int it2 = 0; it2 < 2; ++it2) {
            const int it = ihalf*4 + ith*2 + it2; // 0..7
            float acc[8];
            #pragma unroll
            for (int ii = 0; ii < 8; ++ii) acc[ii] = 0.f;
            #pragma unroll 2
            for (int d = 0; d < DD; ++d) {
                float w = wsm[d*256 + g];
                float4 c0 = *(const float4*)(csm + d*64 + it*8);
                float4 c1 = *(const float4*)(csm + d*64 + it*8 + 4);
                acc[0] += c0.x * w; acc[1] += c0.y * w;
                acc[2] += c0.z * w; acc[3] += c0.w * w;
                acc[4] += c1.x * w; acc[5] += c1.y * w;
                acc[6] += c1.z * w; acc[7] += c1.w * w;
            }
            #pragma unroll
            for (int ii = 0; ii < 8; ++ii)
                out[(n*OO + it*8 + ii)*GD + g] = acc[ii];
        }
    } else {
        float* qsm = fsm;                 // [256]
        float* red = fsm + 256;           // [2][256]
        const int n  = bx - 256;
        const int ks = t >> 8;
        const int g  = t & 255;

        if (t < 256) qsm[t] = ques[n*GD + t];
        __syncthreads();

        const float* base = gw1 + (2*DD + ks*128)*GD + g;
        const float* qb   = qsm + ks*128;
        float a0 = 0.f, a1 = 0.f, a2 = 0.f, a3 = 0.f;
        #pragma unroll 8
        for (int e = 0; e < 128; e += 4) {
            a0 += qb[e]     * base[(e)    *GD];
            a1 += qb[e + 1] * base[(e + 1)*GD];
            a2 += qb[e + 2] * base[(e + 2)*GD];
            a3 += qb[e + 3] * base[(e + 3)*GD];
        }
        red[ks*256 + g] = (a0 + a1) + (a2 + a3);
        __syncthreads();
        if (t < 256)
            d_qc[n*GD + t] = red[t] + red[256 + t] + gb1[t];
    }
}

// ---------------------------------------------------------------------------
// rn_main: fused layers 2-4 per 128-pair tile. grid 2048, 512 threads.
// Warp grid 2x8 (wm x wn), warp tile 64x32. Weight slices per warp-pair:
// warp (0,wn) cp.asyncs B[kchunk][wn*32..+32) into a 2-deep 5KB ring;
// pair syncs via bar.sync(1+wn, 64). Full-CTA barriers only at A-tile
// epilogue boundaries.
// ---------------------------------------------------------------------------
__global__ void __launch_bounds__(512, 1)
rn_main(const float* __restrict__ b2, const float* __restrict__ b3,
        const float* __restrict__ b4) {
    extern __shared__ __nv_bfloat16 sm[];
    __nv_bfloat16* Asm = sm;                      // [128][AS]
    const unsigned AsmS = (unsigned)__cvta_generic_to_shared(sm);

    const int n    = blockIdx.x >> 5;
    const int i0   = (blockIdx.x & 31) << 1;
    const int tid  = threadIdx.x;
    const int lane = tid & 31;
    const int warp = tid >> 5;
    const int wm   = warp >> 3;                   // 0..1 -> 64-row block
    const int wn   = warp & 7;                    // 0..7 -> 32-col block
    // pair slice buffers: (wn*2 + buf) of SLICE_B bytes, after the A tile
    const unsigned sl0 = AsmS + (unsigned)(BO + wn*2*SLICE_B);

    // producer (wm==0) loads chunk c's slice into buffer c&1.
    // chunk c (0..11): layer c/4, k-quarter c&3.
    auto issue = [&](int c) {
        const __nv_bfloat16* W = (c < 4) ? d_w2b : (c < 8) ? d_w3b : d_w4b;
        const __nv_bfloat16* src = W + (c & 3)*KC*GD + wn*32;
        unsigned dst = sl0 + (unsigned)((c & 1) * SLICE_B);
        #pragma unroll
        for (int q = 0; q < 8; ++q) {
            int g  = q*32 + lane;                 // 0..255 granules
            int r  = g >> 2, cg = g & 3;          // row 0..63, 16B col group
            asm volatile("cp.async.cg.shared.global [%0], [%1], 16;"
                         :: "r"(dst + (unsigned)(r*BSTR + cg*8)*2u),
                            "l"(src + r*GD + cg*8));
        }
        asm volatile("cp.async.commit_group;");
    };

    if (wm == 0) issue(0);

    // ---- stage 1: h1 = relu(rowA_i + rowB_j + qc) -> bf16 A tile ----
    {
        const int g  = (tid & 127) * 2;
        const int r0 = tid >> 7;                  // 0..3
        const float2 qv = *(const float2*)(d_qc + n*GD + g);
        float2 A0 = *(const float2*)(d_rowA + (n*OO + i0    )*GD + g);
        float2 A1 = *(const float2*)(d_rowA + (n*OO + i0 + 1)*GD + g);
        A0.x += qv.x; A0.y += qv.y; A1.x += qv.x; A1.y += qv.y;
        #pragma unroll 4
        for (int s = 0; s < 32; ++s) {
            int r = r0 + s*4;
            int j = r & 63;
            float2 B = *(const float2*)(d_rowB + (n*OO + j)*GD + g);
            float vx = ((r >> 6) ? A1.x : A0.x) + B.x;
            float vy = ((r >> 6) ? A1.y : A0.y) + B.y;
            *(__nv_bfloat162*)(Asm + r*AS + g) =
                __floats2bfloat162_rn(fmaxf(vx, 0.f), fmaxf(vy, 0.f));
        }
    }

    if (wm == 0) issue(1);
    __syncthreads();                 // A tile visible to all LDSM readers

    #pragma unroll 1
    for (int layer = 0; layer < 3; ++layer) {
        float C[4][4][4];
        #pragma unroll
        for (int mt = 0; mt < 4; ++mt)
            #pragma unroll
            for (int nt = 0; nt < 4; ++nt) {
                C[mt][nt][0] = 0.f; C[mt][nt][1] = 0.f;
                C[mt][nt][2] = 0.f; C[mt][nt][3] = 0.f;
            }

        #pragma unroll 1
        for (int ch = 0; ch < 4; ++ch) {
            const int c = layer*4 + ch;
            if (wm == 0) {
                if (c < 11) asm volatile("cp.async.wait_group 1;");
                else        asm volatile("cp.async.wait_group 0;");
            }
            bar_pair(1 + wn);         // slice c ready for this pair

            const unsigned bufS = sl0 + (unsigned)((c & 1) * SLICE_B);
            #pragma unroll
            for (int ksl = 0; ksl < 4; ++ksl) {
                const int kb = (c & 3)*KC + ksl*16;   // absolute k in A
                unsigned a[4][4];
                #pragma unroll
                for (int mt = 0; mt < 4; ++mt) {
                    unsigned ad = AsmS +
                        (unsigned)((wm*64 + mt*16 + (lane & 15))*AS
                                   + kb + ((lane >> 4) * 8)) * 2u;
                    ldsm_x4(a[mt], ad);
                }
                unsigned bfr[2][4];
                #pragma unroll
                for (int pr = 0; pr < 2; ++pr) {
                    unsigned bd = bufS +
                        (unsigned)((ksl*16 + (lane & 15))*BSTR
                                   + pr*16 + ((lane >> 4) * 8)) * 2u;
                    ldsm_x4_t(bfr[pr], bd);
                }
                #pragma unroll
                for (int mt = 0; mt < 4; ++mt) {
                    #pragma unroll
                    for (int pr = 0; pr < 2; ++pr) {
                        mma_bf16(C[mt][pr*2    ], a[mt], bfr[pr][0], bfr[pr][1]);
                        mma_bf16(C[mt][pr*2 + 1], a[mt], bfr[pr][2], bfr[pr][3]);
                    }
                }
            }
            bar_pair(1 + wn);         // pair done reading buffer c&1
            if (wm == 0 && c + 2 <= 11) issue(c + 2);
        }
        __syncthreads();              // all warps done reading A this layer

        if (layer < 2) {
            // epilogue: bias + relu -> bf16, in place into A tile
            const float* bias = (layer == 0) ? b2 : b3;
            #pragma unroll
            for (int mt = 0; mt < 4; ++mt) {
                #pragma unroll
                for (int nt = 0; nt < 4; ++nt) {
                    int row = wm*64 + mt*16 + (lane >> 2);
                    int col = wn*32 + nt*8 + (lane & 3)*2;
                    float2 bb = *(const float2*)(bias + col);
                    float v0 = fmaxf(C[mt][nt][0] + bb.x, 0.f);
                    float v1 = fmaxf(C[mt][nt][1] + bb.y, 0.f);
                    float v2 = fmaxf(C[mt][nt][2] + bb.x, 0.f);
                    float v3 = fmaxf(C[mt][nt][3] + bb.y, 0.f);
                    *(__nv_bfloat162*)(Asm + row*AS + col)     = __floats2bfloat162_rn(v0, v1);
                    *(__nv_bfloat162*)(Asm + (row+8)*AS + col) = __floats2bfloat162_rn(v2, v3);
                }
            }
            __syncthreads();          // publish A before next layer's LDSM
        } else {
            // layer 4: bias + relu + column sum straight from fp32 registers
            float* stg = (float*)Asm;    // A tile dead; 2x256 fp32 staging
            #pragma unroll
            for (int nt = 0; nt < 4; ++nt) {
                int col = wn*32 + nt*8 + (lane & 3)*2;
                float2 bb = *(const float2*)(b4 + col);
                float s0 = 0.f, s1 = 0.f;
                #pragma unroll
                for (int mt = 0; mt < 4; ++mt) {
                    s0 += fmaxf(C[mt][nt][0] + bb.x, 0.f)
                        + fmaxf(C[mt][nt][2] + bb.x, 0.f);
                    s1 += fmaxf(C[mt][nt][1] + bb.y, 0.f)
                        + fmaxf(C[mt][nt][3] + bb.y, 0.f);
                }
                #pragma unroll
                for (int off = 16; off >= 4; off >>= 1) {
                    s0 += __shfl_down_sync(0xffffffffu, s0, off);
                    s1 += __shfl_down_sync(0xffffffffu, s1, off);
                }
                if (lane < 4) {
                    int cc = wn*32 + nt*8 + lane*2;
                    stg[wm*GD + cc]     = s0;
                    stg[wm*GD + cc + 1] = s1;
                }
            }
            __syncthreads();
            if (tid < GD)
                d_partial[blockIdx.x*GD + tid] = stg[tid] + stg[GD + tid];
        }
    }
}

// ---------------------------------------------------------------------------
// rn_post: mean -> f-MLP -> log_softmax. grid 64, 1024 threads, k-split x4.
// ---------------------------------------------------------------------------
__global__ void __launch_bounds__(1024, 1)
rn_post(const float* __restrict__ fw1, const float* __restrict__ fb1,
        const float* __restrict__ fw2, const float* __restrict__ fb2,
        const float* __restrict__ fw3, const float* __restrict__ fb3,
        float* __restrict__ out) {
    __shared__ float ctx[GD], acc[1024], y1s[GD], y2s[GD], red[16];
    const int n   = blockIdx.x;
    const int t   = threadIdx.x;
    const int col = t & 255;
    const int q   = t >> 8;                        // k-quarter 0..3

    {
        const float* base = d_partial + (n*32 + q*8)*GD + col;
        float s = 0.f;
        #pragma unroll
        for (int p = 0; p < 8; ++p) s += base[p*GD];
        acc[t] = s;
    }
    __syncthreads();
    if (t < GD)
        ctx[t] = (acc[t] + acc[t+256] + acc[t+512] + acc[t+768]) * (1.0f/4096.0f);
    __syncthreads();

    {
        float a0 = 0.f, a1 = 0.f;
        const float* w = fw1 + (q*64)*GD + col;
        #pragma unroll 8
        for (int k = 0; k < 64; k += 2) {
            a0 += ctx[q*64 + k]     * w[k*GD];
            a1 += ctx[q*64 + k + 1] * w[(k+1)*GD];
        }
        acc[t] = a0 + a1;
    }
    __syncthreads();
    if (t < GD)
        y1s[t] = fmaxf(acc[t] + acc[t+256] + acc[t+512] + acc[t+768] + fb1[t], 0.f);
    __syncthreads();

    {
        float a0 = 0.f, a1 = 0.f;
        const float* w = fw2 + (q*64)*GD + col;
        #pragma unroll 8
        for (int k = 0; k < 64; k += 2) {
            a0 += y1s[q*64 + k]     * w[k*GD];
            a1 += y1s[q*64 + k + 1] * w[(k+1)*GD];
        }
        acc[t] = a0 + a1;
    }
    __syncthreads();
    if (t < GD)
        y2s[t] = fmaxf(acc[t] + acc[t+256] + acc[t+512] + acc[t+768] + fb2[t], 0.f);
    __syncthreads();

    if (t < GD) {
        float p0 = y2s[t] * fw3[t*2 + 0];
        float p1 = y2s[t] * fw3[t*2 + 1];
        #pragma unroll
        for (int o = 16; o > 0; o >>= 1) {
            p0 += __shfl_down_sync(0xffffffffu, p0, o);
            p1 += __shfl_down_sync(0xffffffffu, p1, o);
        }
        if ((t & 31) == 0) { red[t >> 5] = p0; red[8 + (t >> 5)] = p1; }
    }
    __syncthreads();
    if (t == 0) {
        float s0 = fb3[0], s1 = fb3[1];
        #pragma unroll
        for (int w = 0; w < 8; ++w) { s0 += red[w]; s1 += red[8 + w]; }
        float m   = fmaxf(s0, s1);
        float lse = m + logf(expf(s0 - m) + expf(s1 - m));
        out[n*2 + 0] = s0 - lse;
        out[n*2 + 1] = s1 - lse;
    }
}

// ---------------------------------------------------------------------------
extern "C" void kernel_launch(void* const* d_in, const int* in_sizes, int n_in,
                              void* d_out, int out_size) {
    (void)in_sizes; (void)n_in; (void)out_size;
    const float* img  = (const float*)d_in[0];
    const float* ques = (const float*)d_in[1];
    const float* gw1  = (const float*)d_in[2];
    const float* gb1  = (const float*)d_in[3];
    const float* gw2  = (const float*)d_in[4];
    const float* gb2  = (const float*)d_in[5];
    const float* gw3  = (const float*)d_in[6];
    const float* gb3  = (const float*)d_in[7];
    const float* gw4  = (const float*)d_in[8];
    const float* gb4  = (const float*)d_in[9];
    const float* fw1  = (const float*)d_in[10];
    const float* fb1  = (const float*)d_in[11];
    const float* fw2  = (const float*)d_in[12];
    const float* fb2  = (const float*)d_in[13];
    const float* fw3  = (const float*)d_in[14];
    const float* fb3  = (const float*)d_in[15];
    float* out = (float*)d_out;

    cudaFuncSetAttribute(rn_pre,  cudaFuncAttributeMaxDynamicSharedMemorySize, SM_PRE);
    cudaFuncSetAttribute(rn_main, cudaFuncAttributeMaxDynamicSharedMemorySize, SM_MAIN);

    rn_pre  <<<320, 512, SM_PRE>>>(img, ques, gw1, gb1, gw2, gw3, gw4);
    rn_main <<<NCTA, 512, SM_MAIN>>>(gb2, gb3, gb4);
    rn_post <<<NB, 1024>>>(fw1, fb1, fw2, fb2, fw3, fb3, out);
}